// round 11
// baseline (speedup 1.0000x reference)
#include <cuda_runtime.h>

// LBP (radius=1, 8 points, skimage 'default') over NCHW fp32, zero boundary.
// 4x8 strip/thread, block (56,4), grid (1,7,planes), prefetch distance 2,
// guard-free interior y-blocks.
// New vs round 10:
//  - __launch_bounds__(224, 7): 7 blocks/SM at 40 regs (49/64 warps).
//  - threshold transform: diagonal tests drop the WC*c term on the left and
//    compare against cc = (1-WC)*c instead -> shared WE-products, 16 -> ~13
//    fma-pipe ops/px in the bilinear core.

template <bool GUARD>
__device__ __forceinline__ void lbp_strip(
    const float* __restrict__ ip, float* __restrict__ op,
    int x0, int y0, bool has_left, bool has_right)
{
    constexpr int H = 224, W = 224;

    // Bilinear weights (float32 of double products, as jax produces).
    const double Fd = 0.70710678;
    const double Gd = 1.0 - Fd;
    const float WD = (float)(Fd * Fd);
    const float WE = (float)(Fd * Gd);
    const float WC = (float)(Gd * Gd);
    const float KC = 1.0f - WC;          // threshold factor: v' >= KC*c

    // buf[(k+1)&3] holds relative row k, [left, v0..v3, right].
    float buf[4][6];

    const float* base = ip + y0 * W + x0;

    auto load_row = [&](float* b, int k) {
        if (!GUARD || (unsigned)(y0 + k) < (unsigned)H) {
            const float* rp = base + k * W;
            const float4 v = *reinterpret_cast<const float4*>(rp);
            b[0] = has_left  ? __ldg(rp - 1) : 0.0f;
            b[1] = v.x; b[2] = v.y; b[3] = v.z; b[4] = v.w;
            b[5] = has_right ? __ldg(rp + 4) : 0.0f;
        } else {
            b[0] = b[1] = b[2] = b[3] = b[4] = b[5] = 0.0f;
        }
    };

    // Prologue: rows -1, 0, 1.
    load_row(buf[0], -1);
    load_row(buf[1], 0);
    load_row(buf[2], 1);

    float* wp = op + y0 * W + x0;

    #pragma unroll
    for (int r = 0; r < 8; r++) {
        // Prefetch row r+2 (first consumed by compute r+1).
        if (r < 7)
            load_row(buf[(r + 3) & 3], r + 2);

        const float* N = buf[r & 3];
        const float* C = buf[(r + 1) & 3];
        const float* S = buf[(r + 2) & 3];

        float4 res;
        float* resp = &res.x;

        #pragma unroll
        for (int i = 0; i < 4; i++) {
            const float nw = N[i], nn = N[i + 1], ne = N[i + 2];
            const float ww = C[i], c  = C[i + 1], ee = C[i + 2];
            const float sw = S[i], ss = S[i + 1], se = S[i + 2];

            // Shared WE-products (CSE between diagonal pairs and, for
            // te/tw, between neighboring pixels in the row).
            const float tn = WE * nn;
            const float te = WE * ee;
            const float tw = WE * ww;
            const float ts = WE * ss;
            const float cc = KC * c;     // one threshold for all 4 diagonals

            // Center-free diagonal sums (same term order as before, with
            // the WC*c term removed and folded into cc).
            const float v1 = (tn + WD * ne) + te;   // up-right
            const float v3 = (WD * nw + tn) + tw;   // up-left
            const float v5 = (tw + WD * sw) + ts;   // down-left
            const float v7 = (te + ts) + WD * se;   // down-right

            float code = (ee >= c) ? 1.0f : 0.0f;   // p=0: east
            if (v1 >= cc) code += 2.0f;             // p=1
            if (nn >= c)  code += 4.0f;             // p=2: north
            if (v3 >= cc) code += 8.0f;             // p=3
            if (ww >= c)  code += 16.0f;            // p=4: west
            if (v5 >= cc) code += 32.0f;            // p=5
            if (ss >= c)  code += 64.0f;            // p=6: south
            if (v7 >= cc) code += 128.0f;           // p=7
            resp[i] = code;
        }

        __stcs(reinterpret_cast<float4*>(wp), res);  // streaming store
        wp += W;
    }
}

__global__ __launch_bounds__(224, 7) void lbp_kernel(
    const float* __restrict__ in, float* __restrict__ out)
{
    constexpr int H = 224, W = 224;

    const int plane = blockIdx.z;
    const float* ip = in + (size_t)plane * (H * W);
    float*       op = out + (size_t)plane * (H * W);

    const int tx = threadIdx.x;                        // column group 0..55
    const int x0 = tx * 4;
    const int by = blockIdx.y;
    const int y0 = by * 32 + threadIdx.y * 8;          // strip row base

    const bool has_left  = (tx > 0);
    const bool has_right = (tx < 55);

    if (by >= 1 && by <= 5) {
        // Interior: rows y0-1 .. y0+8 all within [0, 223] -> no bounds checks.
        lbp_strip<false>(ip, op, x0, y0, has_left, has_right);
    } else {
        lbp_strip<true>(ip, op, x0, y0, has_left, has_right);
    }
}

extern "C" void kernel_launch(void* const* d_in, const int* in_sizes, int n_in,
                              void* d_out, int out_size)
{
    const float* x = (const float*)d_in[0];
    float* out = (float*)d_out;

    constexpr int H = 224, W = 224;
    const int planes = out_size / (H * W);   // B*C = 1024

    dim3 block(56, 4, 1);                    // 224 threads = 7 warps
    dim3 grid(1, 7, planes);
    lbp_kernel<<<grid, block>>>(x, out);
}

// round 12
// speedup vs baseline: 1.1046x; 1.1046x over previous
#include <cuda_runtime.h>

// LBP (radius=1, 8 points, skimage 'default') over NCHW fp32, zero boundary.
// 4x8 strip/thread, block (56,4), grid (1,7,planes), prefetch distance 2,
// guard-free interior y-blocks.
// Round 12 = round 10 occupancy config (__launch_bounds__(224, 6), regs~40,
// the measured best) + round 11 threshold algebra (center term folded into
// the comparison threshold; shared WE-products): 16 -> ~13 fma ops/px.

template <bool GUARD>
__device__ __forceinline__ void lbp_strip(
    const float* __restrict__ ip, float* __restrict__ op,
    int x0, int y0, bool has_left, bool has_right)
{
    constexpr int H = 224, W = 224;

    // Bilinear weights (float32 of double products, as jax produces).
    const double Fd = 0.70710678;
    const double Gd = 1.0 - Fd;
    const float WD = (float)(Fd * Fd);
    const float WE = (float)(Fd * Gd);
    const float WC = (float)(Gd * Gd);
    const float KC = 1.0f - WC;          // threshold factor: v' >= KC*c

    // buf[(k+1)&3] holds relative row k, [left, v0..v3, right].
    float buf[4][6];

    const float* base = ip + y0 * W + x0;

    auto load_row = [&](float* b, int k) {
        if (!GUARD || (unsigned)(y0 + k) < (unsigned)H) {
            const float* rp = base + k * W;
            const float4 v = *reinterpret_cast<const float4*>(rp);
            b[0] = has_left  ? __ldg(rp - 1) : 0.0f;
            b[1] = v.x; b[2] = v.y; b[3] = v.z; b[4] = v.w;
            b[5] = has_right ? __ldg(rp + 4) : 0.0f;
        } else {
            b[0] = b[1] = b[2] = b[3] = b[4] = b[5] = 0.0f;
        }
    };

    // Prologue: rows -1, 0, 1.
    load_row(buf[0], -1);
    load_row(buf[1], 0);
    load_row(buf[2], 1);

    float* wp = op + y0 * W + x0;

    #pragma unroll
    for (int r = 0; r < 8; r++) {
        // Prefetch row r+2 (first consumed by compute r+1).
        if (r < 7)
            load_row(buf[(r + 3) & 3], r + 2);

        const float* N = buf[r & 3];
        const float* C = buf[(r + 1) & 3];
        const float* S = buf[(r + 2) & 3];

        float4 res;
        float* resp = &res.x;

        #pragma unroll
        for (int i = 0; i < 4; i++) {
            const float nw = N[i], nn = N[i + 1], ne = N[i + 2];
            const float ww = C[i], c  = C[i + 1], ee = C[i + 2];
            const float sw = S[i], ss = S[i + 1], se = S[i + 2];

            // Shared WE-products (CSE between diagonal pairs).
            const float tn = WE * nn;
            const float te = WE * ee;
            const float tw = WE * ww;
            const float ts = WE * ss;
            const float cc = KC * c;     // one threshold for all 4 diagonals

            // Center-free diagonal sums.
            const float v1 = (tn + WD * ne) + te;   // up-right
            const float v3 = (WD * nw + tn) + tw;   // up-left
            const float v5 = (tw + WD * sw) + ts;   // down-left
            const float v7 = (te + ts) + WD * se;   // down-right

            float code = (ee >= c) ? 1.0f : 0.0f;   // p=0: east
            if (v1 >= cc) code += 2.0f;             // p=1
            if (nn >= c)  code += 4.0f;             // p=2: north
            if (v3 >= cc) code += 8.0f;             // p=3
            if (ww >= c)  code += 16.0f;            // p=4: west
            if (v5 >= cc) code += 32.0f;            // p=5
            if (ss >= c)  code += 64.0f;            // p=6: south
            if (v7 >= cc) code += 128.0f;           // p=7
            resp[i] = code;
        }

        __stcs(reinterpret_cast<float4*>(wp), res);  // streaming store
        wp += W;
    }
}

__global__ __launch_bounds__(224, 6) void lbp_kernel(
    const float* __restrict__ in, float* __restrict__ out)
{
    constexpr int H = 224, W = 224;

    const int plane = blockIdx.z;
    const float* ip = in + (size_t)plane * (H * W);
    float*       op = out + (size_t)plane * (H * W);

    const int tx = threadIdx.x;                        // column group 0..55
    const int x0 = tx * 4;
    const int by = blockIdx.y;
    const int y0 = by * 32 + threadIdx.y * 8;          // strip row base

    const bool has_left  = (tx > 0);
    const bool has_right = (tx < 55);

    if (by >= 1 && by <= 5) {
        // Interior: rows y0-1 .. y0+8 all within [0, 223] -> no bounds checks.
        lbp_strip<false>(ip, op, x0, y0, has_left, has_right);
    } else {
        lbp_strip<true>(ip, op, x0, y0, has_left, has_right);
    }
}

extern "C" void kernel_launch(void* const* d_in, const int* in_sizes, int n_in,
                              void* d_out, int out_size)
{
    const float* x = (const float*)d_in[0];
    float* out = (float*)d_out;

    constexpr int H = 224, W = 224;
    const int planes = out_size / (H * W);   // B*C = 1024

    dim3 block(56, 4, 1);                    // 224 threads = 7 warps
    dim3 grid(1, 7, planes);
    lbp_kernel<<<grid, block>>>(x, out);
}